// round 1
// baseline (speedup 1.0000x reference)
#include <cuda_runtime.h>
#include <math.h>

#define BATCH 256
#define SEQ   256
#define IDIM  128
#define HID   1024
#define OUTC  10

#define NCTA  128
#define NTH   128
#define MT    64
#define NT    32
#define KC    16
#define NCHUNK_H (HID / KC)            // 64
#define NCHUNK_X (IDIM / KC)           // 8
#define NCHUNK   (NCHUNK_H + NCHUNK_X) // 72

// Persistent state (device globals: no allocation allowed)
__device__ float g_h[2][BATCH][HID];       // double-buffered hidden state, 2 MB
__device__ unsigned int g_bar;             // monotonic ticket barrier counter

// ---- packed f32x2 helpers (Blackwell dual-issue fp32) ----
__device__ __forceinline__ unsigned long long splat2(float x) {
    unsigned long long r;
    asm("mov.b64 %0, {%1, %1};" : "=l"(r) : "f"(x));
    return r;
}
__device__ __forceinline__ void fma2(unsigned long long& acc,
                                     unsigned long long a,
                                     unsigned long long b) {
    asm("fma.rn.f32x2 %0, %1, %2, %0;" : "+l"(acc) : "l"(a), "l"(b));
}
__device__ __forceinline__ float2 unpk(unsigned long long v) {
    float2 r;
    asm("mov.b64 {%0, %1}, %2;" : "=f"(r.x), "=f"(r.y) : "l"(v));
    return r;
}

// Accurate-enough tanh independent of --use_fast_math's tanh.approx.
// abs error ~5e-7 everywhere (MUFU.EX2 + MUFU.RCP based).
__device__ __forceinline__ float my_tanh(float v) {
    float e = __expf(2.0f * v);
    return 1.0f - 2.0f / (e + 1.0f);
}

// Device-wide barrier: monotonic ticket counter (no reset -> survives CUDA
// graph replays; each launch performs the same number of barriers so the
// counter stays a multiple of NCTA at launch boundaries).
__device__ __forceinline__ void grid_sync() {
    __syncthreads();
    if (threadIdx.x == 0) {
        __threadfence();                                   // release
        unsigned ticket = atomicAdd(&g_bar, 1u);
        unsigned target = (ticket / NCTA + 1u) * NCTA;
        volatile unsigned* p = &g_bar;
        while (*p < target) { }
    }
    __syncthreads();
    __threadfence();                                       // acquire
}

__global__ void __launch_bounds__(NTH, 1)
rnn_kernel(const float* __restrict__ x,      // [B,S,I]
           const float* __restrict__ Whx,    // [I,H]
           const float* __restrict__ Whh,    // [H,H]
           const float* __restrict__ bh,     // [H]
           const float* __restrict__ Why,    // [H,OUT]
           const float* __restrict__ bo,     // [OUT]
           float* __restrict__ out)          // [B,OUT]
{
    __shared__ __align__(16) float As[2][KC][MT + 4];   // k-major A tile (+pad)
    __shared__ __align__(16) float Bs[2][KC][NT];
    __shared__ float red[4][OUTC];

    const int tid = threadIdx.x;
    const int bid = blockIdx.x;
    const int mt = bid & 3;          // 4 M-tiles of 64
    const int nt = bid >> 2;         // 32 N-tiles of 32
    const int m0 = mt * MT;
    const int n0 = nt * NT;

    // global->smem loader lanes
    const int la_m  = tid >> 2;            // 0..31 (row; +32 for 2nd half)
    const int la_kt = (tid & 3) * 4;       // 0,4,8,12 (k quad)
    const int lb_k  = tid >> 3;            // 0..15
    const int lb_n  = (tid & 7) * 4;       // 0..28

    // compute lanes: 4x4 micro-tile (rows 4*ty.., cols 4*tx..)
    const int tx = tid & 7;                // 8  -> 32 cols
    const int ty = tid >> 3;               // 16 -> 64 rows

    // ---- zero h buffer 0 (h0 = 0); must re-run every launch ----
    {
        float4* p = (float4*)&g_h[0][0][0];
        const int total = BATCH * HID / 4;
        for (int i = bid * NTH + tid; i < total; i += NCTA * NTH)
            p[i] = make_float4(0.f, 0.f, 0.f, 0.f);
    }
    grid_sync();

    unsigned long long acc[2][4];

    for (int t = 0; t < SEQ; t++) {
        const float* __restrict__ hcur = &g_h[t & 1][0][0];
        float* __restrict__ hnxt = &g_h[(t + 1) & 1][0][0];
        const float* __restrict__ xt = x + t * IDIM;   // x[:, t, :], row stride S*I

        #pragma unroll
        for (int p = 0; p < 2; p++)
            #pragma unroll
            for (int j = 0; j < 4; j++)
                acc[p][j] = 0ull;

        float4 pA0, pA1, pB;

        // prefetch + store chunk 0 (h part, k0 = 0)
        pA0 = *(const float4*)(hcur + (m0 + la_m) * HID + la_kt);
        pA1 = *(const float4*)(hcur + (m0 + la_m + 32) * HID + la_kt);
        pB  = *(const float4*)(Whh + lb_k * HID + n0 + lb_n);

        As[0][la_kt + 0][la_m] = pA0.x;
        As[0][la_kt + 1][la_m] = pA0.y;
        As[0][la_kt + 2][la_m] = pA0.z;
        As[0][la_kt + 3][la_m] = pA0.w;
        As[0][la_kt + 0][la_m + 32] = pA1.x;
        As[0][la_kt + 1][la_m + 32] = pA1.y;
        As[0][la_kt + 2][la_m + 32] = pA1.z;
        As[0][la_kt + 3][la_m + 32] = pA1.w;
        *(float4*)&Bs[0][lb_k][lb_n] = pB;
        __syncthreads();

        for (int c = 0; c < NCHUNK; c++) {
            const int cb = c & 1;
            const int cn = c + 1;

            // prefetch next chunk into registers (hidden under compute)
            if (cn < NCHUNK) {
                if (cn < NCHUNK_H) {
                    const int k0 = cn * KC;
                    pA0 = *(const float4*)(hcur + (m0 + la_m) * HID + k0 + la_kt);
                    pA1 = *(const float4*)(hcur + (m0 + la_m + 32) * HID + k0 + la_kt);
                    pB  = *(const float4*)(Whh + (k0 + lb_k) * HID + n0 + lb_n);
                } else {
                    const int k0 = (cn - NCHUNK_H) * KC;
                    pA0 = *(const float4*)(xt + (m0 + la_m) * (SEQ * IDIM) + k0 + la_kt);
                    pA1 = *(const float4*)(xt + (m0 + la_m + 32) * (SEQ * IDIM) + k0 + la_kt);
                    pB  = *(const float4*)(Whx + (k0 + lb_k) * HID + n0 + lb_n);
                }
            }

            // compute 16 k-steps from smem buffer cb
            #pragma unroll
            for (int kk = 0; kk < KC; kk++) {
                ulonglong2 av = *(const ulonglong2*)&As[cb][kk][4 * ty];
                float4 bv = *(const float4*)&Bs[cb][kk][4 * tx];
                unsigned long long b0 = splat2(bv.x);
                unsigned long long b1 = splat2(bv.y);
                unsigned long long b2 = splat2(bv.z);
                unsigned long long b3 = splat2(bv.w);
                fma2(acc[0][0], av.x, b0);
                fma2(acc[0][1], av.x, b1);
                fma2(acc[0][2], av.x, b2);
                fma2(acc[0][3], av.x, b3);
                fma2(acc[1][0], av.y, b0);
                fma2(acc[1][1], av.y, b1);
                fma2(acc[1][2], av.y, b2);
                fma2(acc[1][3], av.y, b3);
            }

            // stage next chunk into the other smem buffer
            if (cn < NCHUNK) {
                const int nb = cn & 1;
                As[nb][la_kt + 0][la_m] = pA0.x;
                As[nb][la_kt + 1][la_m] = pA0.y;
                As[nb][la_kt + 2][la_m] = pA0.z;
                As[nb][la_kt + 3][la_m] = pA0.w;
                As[nb][la_kt + 0][la_m + 32] = pA1.x;
                As[nb][la_kt + 1][la_m + 32] = pA1.y;
                As[nb][la_kt + 2][la_m + 32] = pA1.z;
                As[nb][la_kt + 3][la_m + 32] = pA1.w;
                *(float4*)&Bs[nb][lb_k][lb_n] = pB;
            }
            __syncthreads();
        }

        // epilogue: bias + tanh + store h_next
        {
            float4 bhv = *(const float4*)(bh + n0 + 4 * tx);
            #pragma unroll
            for (int p = 0; p < 2; p++) {
                float2 c0 = unpk(acc[p][0]);
                float2 c1 = unpk(acc[p][1]);
                float2 c2 = unpk(acc[p][2]);
                float2 c3 = unpk(acc[p][3]);
                const int r = m0 + 4 * ty + 2 * p;
                float4 lo = make_float4(my_tanh(c0.x + bhv.x), my_tanh(c1.x + bhv.y),
                                        my_tanh(c2.x + bhv.z), my_tanh(c3.x + bhv.w));
                float4 hi = make_float4(my_tanh(c0.y + bhv.x), my_tanh(c1.y + bhv.y),
                                        my_tanh(c2.y + bhv.z), my_tanh(c3.y + bhv.w));
                *(float4*)(hnxt + r * HID + n0 + 4 * tx) = lo;
                *(float4*)(hnxt + (r + 1) * HID + n0 + 4 * tx) = hi;
            }
        }
        grid_sync();
    }

    // ---- classifier + softmax: 2 rows per CTA ----
    const float* hf = &g_h[0][0][0];   // (SEQ & 1)==0 -> final h lives in buf 0
    const int lane = tid & 31;
    const int wrp  = tid >> 5;
    for (int rr = 0; rr < 2; rr++) {
        const int row = bid * 2 + rr;
        float a[OUTC];
        #pragma unroll
        for (int o = 0; o < OUTC; o++) a[o] = 0.f;
        for (int k = tid; k < HID; k += NTH) {
            float hv = hf[row * HID + k];
            const float* wr = Why + k * OUTC;
            #pragma unroll
            for (int o = 0; o < OUTC; o++) a[o] += hv * wr[o];
        }
        #pragma unroll
        for (int o = 0; o < OUTC; o++)
            #pragma unroll
            for (int off = 16; off > 0; off >>= 1)
                a[o] += __shfl_down_sync(0xffffffffu, a[o], off);
        if (lane == 0) {
            #pragma unroll
            for (int o = 0; o < OUTC; o++) red[wrp][o] = a[o];
        }
        __syncthreads();
        if (tid == 0) {
            float v[OUTC];
            float mx = -1e30f;
            #pragma unroll
            for (int o = 0; o < OUTC; o++) {
                v[o] = red[0][o] + red[1][o] + red[2][o] + red[3][o] + bo[o];
                mx = fmaxf(mx, v[o]);
            }
            float s = 0.f;
            #pragma unroll
            for (int o = 0; o < OUTC; o++) { v[o] = expf(v[o] - mx); s += v[o]; }
            const float inv = 1.0f / s;
            #pragma unroll
            for (int o = 0; o < OUTC; o++) out[row * OUTC + o] = v[o] * inv;
        }
        __syncthreads();
    }
}

extern "C" void kernel_launch(void* const* d_in, const int* in_sizes, int n_in,
                              void* d_out, int out_size) {
    const float* x   = (const float*)d_in[0];
    const float* Whx = (const float*)d_in[1];
    const float* Whh = (const float*)d_in[2];
    const float* bh  = (const float*)d_in[3];
    const float* Why = (const float*)d_in[4];
    const float* bo  = (const float*)d_in[5];
    float* out = (float*)d_out;
    rnn_kernel<<<NCTA, NTH>>>(x, Whx, Whh, bh, Why, bo, out);
}